// round 4
// baseline (speedup 1.0000x reference)
#include <cuda_runtime.h>
#include <math.h>

// Problem constants (fixed by the bench problem)
#define AA     48          // atoms per batch
#define SS     4           // num species
#define NR     16          // num radial shifts (ShfR)
#define NAA    4           // num angular radial shifts (ShfA)
#define NZ     8           // num angular shifts (ShfZ)
#define NPAIRS (SS*(SS+1)/2)   // 10
#define RADD   (SS*NR)         // 64
#define ANGD   (NPAIRS*NAA*NZ) // 320
#define OUTD   (RADD+ANGD)     // 384
#define RCR    5.2f
#define RCA    3.5f
#define PI_F   3.14159265358979323846f

#define ROLES    6          // 2 radial (ShfR halves) + 4 angular (ShfZ pairs)
#define NRH      8          // ShfR per radial role
#define NZH      2          // ShfZ per angular role

__global__ __launch_bounds__(128) void aev_kernel(
    const int*   __restrict__ species,   // [B, A]
    const float* __restrict__ coords,    // [B, A, 3]
    const float* __restrict__ EtaR,      // [1]
    const float* __restrict__ ShfR,      // [NR]
    const float* __restrict__ EtaA,      // [1]
    const float* __restrict__ Zeta,      // [1]
    const float* __restrict__ ShfA,      // [NAA]
    const float* __restrict__ ShfZ,      // [NZ]
    float*       __restrict__ out)       // [B, A, OUTD]
{
    __shared__ float cxs[AA], cys[AA], czs_[AA];
    __shared__ int   sp[AA];
    __shared__ int   cnt;

    const int tid  = threadIdx.x;
    const int bd   = blockDim.x;
    const int role = blockIdx.x % ROLES;
    const int aidx = blockIdx.x / ROLES;    // global atom index
    const int i    = aidx % AA;
    const int b    = aidx / AA;

    if (tid == 0) cnt = 0;
    if (tid < AA) {
        cxs[tid]  = coords[(b*AA + tid)*3 + 0];
        cys[tid]  = coords[(b*AA + tid)*3 + 1];
        czs_[tid] = coords[(b*AA + tid)*3 + 2];
        sp[tid]   = species[b*AA + tid];
    }
    __syncthreads();

    const bool  validI = (sp[i] >= 0);
    const float xi = cxs[i], yi = cys[i], zi = czs_[i];
    float* o = out + (size_t)aidx * OUTD;

    if (role < 2) {
        // ============ RADIAL role: ShfR slice [rbase, rbase+8) ============
        const int rbase = role * NRH;
        __shared__ float rd[AA], rf[AA];
        __shared__ int   rs[AA];
        __shared__ float accR[SS*NRH];          // 32
        __shared__ float shfR_s[NRH];
        __shared__ float etaR_sh;

        if (tid == 0) etaR_sh = EtaR[0];
        if (tid < NRH) shfR_s[tid] = ShfR[rbase + tid];
        if (tid < SS*NRH) accR[tid] = 0.0f;

        if (tid < AA) {
            int j = tid;
            float dx = xi - cxs[j], dy = yi - cys[j], dz = zi - czs_[j];
            float d  = sqrtf(dx*dx + dy*dy + dz*dz);
            bool ok = validI && (sp[j] >= 0) && (j != i) && (d <= RCR);
            if (ok) {
                int s = atomicAdd(&cnt, 1);
                rd[s] = d;
                rf[s] = 0.5f*__cosf(PI_F * d * (1.0f/RCR)) + 0.5f;
                rs[s] = sp[j];
            }
        }
        __syncthreads();

        const int   Mr   = cnt;
        const float etaR = etaR_sh;
        for (int w = tid; w < Mr*NRH; w += bd) {
            int j = w >> 3;        // NRH == 8
            int r = w & 7;
            float dd = rd[j] - shfR_s[r];
            float v  = 0.25f * __expf(-etaR * dd * dd) * rf[j];
            atomicAdd(&accR[rs[j]*NRH + r], v);
        }
        __syncthreads();

        if (tid < SS*NRH) {
            int s = tid >> 3, r = tid & 7;
            o[s*NR + rbase + r] = accR[tid];
        }
    } else {
        // ============ ANGULAR role: ShfZ slice {zbase, zbase+1} ============
        const int zbase = (role - 2) * NZH;
        __shared__ float dxs[AA], dys[AA], dzs[AA], dst[AA], fca[AA];
        __shared__ int   nbr[AA];
        __shared__ float accA[NPAIRS*NAA*NZH];  // 80
        __shared__ float shfA_s[NAA];
        __shared__ float cz0, sz0, cz1, sz1;
        __shared__ float etaA_sh, zeta_sh;

        if (tid == 0) {
            etaA_sh = EtaA[0]; zeta_sh = Zeta[0];
            float s0 = ShfZ[zbase], s1 = ShfZ[zbase + 1];
            cz0 = __cosf(s0); sz0 = __sinf(s0);
            cz1 = __cosf(s1); sz1 = __sinf(s1);
        }
        if (tid < NAA) shfA_s[tid] = ShfA[tid];
        if (tid < NPAIRS*NAA*NZH) accA[tid] = 0.0f;

        if (tid < AA) {
            int j = tid;
            float dx = xi - cxs[j], dy = yi - cys[j], dz = zi - czs_[j];
            float d  = sqrtf(dx*dx + dy*dy + dz*dz);
            bool an = validI && (sp[j] >= 0) && (j != i) && (d <= RCA);
            if (an) {
                int s = atomicAdd(&cnt, 1);
                nbr[s] = j;
                dxs[j] = dx; dys[j] = dy; dzs[j] = dz; dst[j] = d;
                fca[j] = 0.5f*__cosf(PI_F * d * (1.0f/RCA)) + 0.5f;
            }
        }
        __syncthreads();

        const int   M      = cnt;
        const int   npair2 = M*(M-1)/2;
        const float etaA   = etaA_sh;
        const float zeta   = zeta_sh;

        // Fused per-pair body: geometry + Gaussians + 2 z-terms + 8 atomics
        for (int u = tid; u < npair2; u += bd) {
            int p = 0, rem = u;
            while (rem >= M - 1 - p) { rem -= M - 1 - p; p++; }
            int q  = p + 1 + rem;
            int jp = nbr[p], jq = nbr[q];

            float dp = dst[jp], dq = dst[jq];
            float dot = dxs[jp]*dxs[jq] + dys[jp]*dys[jq] + dzs[jp]*dzs[jq];
            float dd  = fmaxf(dp*dq, 1e-8f);
            float cosA = 0.95f * dot * __frcp_rn(dd);
            float sinA = sqrtf(fmaxf(1.0f - cosA*cosA, 0.0f));
            float dsum = 0.5f * (dp + dq);
            float w2   = 2.0f * fca[jp] * fca[jq];

            int s1 = sp[jp], s2 = sp[jq];
            int lo = min(s1, s2), hi = max(s1, s2);
            int pidx = lo*SS - (lo*(lo-1))/2 + (hi - lo);
            int base = pidx * (NAA*NZH);

            float f2v[NAA];
            #pragma unroll
            for (int a = 0; a < NAA; a++) {
                float t = dsum - shfA_s[a];
                f2v[a] = w2 * __expf(-etaA * t * t);
            }

            #pragma unroll
            for (int zz = 0; zz < NZH; zz++) {
                float czv = zz ? cz1 : cz0;
                float szv = zz ? sz1 : sz0;
                float x = 0.5f * (1.0f + cosA*czv + sinA*szv);
                float f1;
                if (zeta == 32.0f) {
                    float x2 = x*x, x4 = x2*x2, x8 = x4*x4, x16 = x8*x8;
                    f1 = x16*x16;
                } else {
                    f1 = __powf(x, zeta);
                }
                #pragma unroll
                for (int a = 0; a < NAA; a++) {
                    atomicAdd(&accA[base + a*NZH + zz], f1 * f2v[a]);
                }
            }
        }
        __syncthreads();

        // write this role's z-columns: feature = pa*NZ + zbase + zz, pa = pidx*NAA + a
        if (tid < NPAIRS*NAA*NZH) {
            int pa = tid >> 1;       // NZH == 2
            int zz = tid & 1;
            o[RADD + pa*NZ + zbase + zz] = accA[tid];
        }
    }
}

extern "C" void kernel_launch(void* const* d_in, const int* in_sizes, int n_in,
                              void* d_out, int out_size)
{
    const int*   species = (const int*)  d_in[0];
    const float* coords  = (const float*)d_in[1];
    const float* EtaR    = (const float*)d_in[2];
    const float* ShfR    = (const float*)d_in[3];
    const float* EtaA    = (const float*)d_in[4];
    const float* Zeta    = (const float*)d_in[5];
    const float* ShfA    = (const float*)d_in[6];
    const float* ShfZ    = (const float*)d_in[7];
    float* out = (float*)d_out;

    int B = in_sizes[0] / AA;   // species is [B, A]
    aev_kernel<<<B * AA * ROLES, 128>>>(species, coords, EtaR, ShfR, EtaA, Zeta,
                                        ShfA, ShfZ, out);
}

// round 5
// speedup vs baseline: 1.2820x; 1.2820x over previous
#include <cuda_runtime.h>
#include <math.h>

// Problem constants (fixed by the bench problem)
#define AA     48          // atoms per batch
#define SS     4           // num species
#define NR     16          // num radial shifts (ShfR)
#define NAA    4           // num angular radial shifts (ShfA)
#define NZ     8           // num angular shifts (ShfZ)
#define NPAIRS (SS*(SS+1)/2)   // 10
#define RADD   (SS*NR)         // 64
#define ANGD   (NPAIRS*NAA*NZ) // 320
#define OUTD   (RADD+ANGD)     // 384
#define RCR    5.2f
#define RCA    3.5f
#define PI_F   3.14159265358979323846f
#define PCHUNK 128

#define BAR_SYNC(id) asm volatile("bar.sync %0, 128;" :: "r"(id) : "memory")

__global__ __launch_bounds__(256) void aev_kernel(
    const int*   __restrict__ species,   // [B, A]
    const float* __restrict__ coords,    // [B, A, 3]
    const float* __restrict__ EtaR,      // [1]
    const float* __restrict__ ShfR,      // [NR]
    const float* __restrict__ EtaA,      // [1]
    const float* __restrict__ Zeta,      // [1]
    const float* __restrict__ ShfA,      // [NAA]
    const float* __restrict__ ShfZ,      // [NZ]
    float*       __restrict__ out)       // [B, A, OUTD]
{
    __shared__ float cxyz[AA*3];
    __shared__ int   sp[AA];
    __shared__ int   cntR, cntA;
    // radial compacted
    __shared__ float rd[AA], rf[AA];
    __shared__ int   rs[AA];
    __shared__ float accR[RADD];
    __shared__ float shfR_s[NR];
    // angular compacted (indexed by slot)
    __shared__ float adx[AA], ady[AA], adz[AA], ad[AA], afc[AA];
    __shared__ int   spA[AA];
    __shared__ float accA[ANGD];
    __shared__ float shfA_s[NAA], czZ[NZ], szZ[NZ];
    __shared__ float etaR_sh, etaA_sh, zeta_sh;
    // angular phase staging
    __shared__ float pcos[PCHUNK], psin[PCHUNK];
    __shared__ int   pbase[PCHUNK];
    __shared__ float pf2[PCHUNK][NAA];

    const int tid  = threadIdx.x;
    const int aidx = blockIdx.x;       // global atom index
    const int i    = aidx % AA;
    const int b    = aidx / AA;

    // ---------------- shared prologue (all 256 threads) ----------------
    if (tid == 0) {
        cntR = 0; cntA = 0;
        etaR_sh = EtaR[0]; etaA_sh = EtaA[0]; zeta_sh = Zeta[0];
    }
    if (tid < 36) ((float4*)cxyz)[tid] = ((const float4*)(coords + (size_t)b*AA*3))[tid];
    if (tid < AA) sp[tid] = species[b*AA + tid];
    if (tid < NR) shfR_s[tid] = ShfR[tid];
    if (tid < NAA) shfA_s[tid] = ShfA[tid];
    if (tid < NZ) { float s = ShfZ[tid]; czZ[tid] = __cosf(s); szZ[tid] = __sinf(s); }
    if (tid < RADD) accR[tid] = 0.0f;
    if (tid >= 128 && tid < 128 + ANGD - 128) accA[tid - 128 + 128] = 0.0f;  // part
    if (tid < 128) accA[tid] = 0.0f;
    if (tid >= 128) { int t = tid + ANGD - 256; if (t >= 128 && t < ANGD) accA[t] = 0.0f; }
    __syncthreads();

    const bool  validI = (sp[i] >= 0);
    const float xi = cxyz[3*i], yi = cxyz[3*i+1], zi = cxyz[3*i+2];

    if (tid < AA) {
        int j = tid;
        float dx = xi - cxyz[3*j], dy = yi - cxyz[3*j+1], dz = zi - cxyz[3*j+2];
        float d  = sqrtf(dx*dx + dy*dy + dz*dz);
        bool pv = validI && (sp[j] >= 0) && (j != i);
        if (pv && d <= RCR) {
            int s = atomicAdd(&cntR, 1);
            rd[s] = d;
            rf[s] = 0.5f*__cosf(PI_F * d * (1.0f/RCR)) + 0.5f;
            rs[s] = sp[j];
        }
        if (pv && d <= RCA) {
            int s = atomicAdd(&cntA, 1);
            adx[s] = dx; ady[s] = dy; adz[s] = dz; ad[s] = d;
            afc[s] = 0.5f*__cosf(PI_F * d * (1.0f/RCA)) + 0.5f;
            spA[s] = sp[j];
        }
    }
    __syncthreads();

    if (tid < 128) {
        // ================= RADIAL half: out[0..RADD) =================
        const int   Mr   = cntR;
        const float etaR = etaR_sh;
        for (int w = tid; w < Mr*NR; w += 128) {
            int j = w >> 4;        // NR == 16
            int r = w & 15;
            float dd = rd[j] - shfR_s[r];
            float v  = 0.25f * __expf(-etaR * dd * dd) * rf[j];
            atomicAdd(&accR[rs[j]*NR + r], v);
        }
        BAR_SYNC(1);
        float* o = out + (size_t)aidx * OUTD;
        if (tid < RADD) o[tid] = accR[tid];
    } else {
        // ================= ANGULAR half: out[RADD..OUTD) =================
        const int   t2     = tid - 128;
        const int   M      = cntA;
        const int   npair2 = M*(M-1)/2;
        const float etaA   = etaA_sh;
        const float zeta   = zeta_sh;
        const float twoM1  = (float)(2*M - 1);

        for (int u0 = 0; u0 < npair2 || u0 == 0; u0 += PCHUNK) {
            const int chunkN = min(PCHUNK, npair2 - u0);

            // Phase A: one thread per pair
            if (t2 < chunkN) {
                int u = u0 + t2;
                // closed-form decode of (p,q) with O(1) fixup
                float disc = twoM1*twoM1 - 8.0f*(float)u;
                int p = (int)floorf((twoM1 - __fsqrt_rn(disc)) * 0.5f);
                if ((p+1)*(2*M - p - 2) / 2 <= u) p++;
                if (p*(2*M - p - 1) / 2 > u) p--;
                int q = u - p*(2*M - p - 1)/2 + p + 1;

                float dp = ad[p], dq = ad[q];
                float dot = adx[p]*adx[q] + ady[p]*ady[q] + adz[p]*adz[q];
                float dd  = fmaxf(dp*dq, 1e-8f);
                float cosA = 0.95f * __fdividef(dot, dd);
                float sinA = sqrtf(fmaxf(1.0f - cosA*cosA, 0.0f));
                float dsum = 0.5f * (dp + dq);
                float w2   = 2.0f * afc[p] * afc[q];

                int s1 = spA[p], s2 = spA[q];
                int lo = min(s1, s2), hi = max(s1, s2);
                int pidx = lo*SS - (lo*(lo-1))/2 + (hi - lo);

                pcos[t2]  = cosA;
                psin[t2]  = sinA;
                pbase[t2] = pidx*(NAA*NZ);
                #pragma unroll
                for (int a = 0; a < NAA; a++) {
                    float t = dsum - shfA_s[a];
                    pf2[t2][a] = w2 * __expf(-etaA * t * t);
                }
            }
            BAR_SYNC(2);

            // Phase B: one thread per (pair, z)
            const int nItems = chunkN * NZ;
            for (int w = t2; w < nItems; w += 128) {
                int u = w >> 3;           // NZ == 8
                int z = w & 7;
                float x = 0.5f * (1.0f + pcos[u]*czZ[z] + psin[u]*szZ[z]);
                float f1;
                if (zeta == 32.0f) {
                    float x2 = x*x, x4 = x2*x2, x8 = x4*x4, x16 = x8*x8;
                    f1 = x16*x16;
                } else {
                    f1 = __powf(x, zeta);
                }
                int base = pbase[u] + z;
                #pragma unroll
                for (int a = 0; a < NAA; a++) {
                    atomicAdd(&accA[base + a*NZ], f1 * pf2[u][a]);
                }
            }
            BAR_SYNC(2);
        }

        float* o = out + (size_t)aidx * OUTD + RADD;
        for (int t = t2; t < ANGD; t += 128) o[t] = accA[t];
    }
}

extern "C" void kernel_launch(void* const* d_in, const int* in_sizes, int n_in,
                              void* d_out, int out_size)
{
    const int*   species = (const int*)  d_in[0];
    const float* coords  = (const float*)d_in[1];
    const float* EtaR    = (const float*)d_in[2];
    const float* ShfR    = (const float*)d_in[3];
    const float* EtaA    = (const float*)d_in[4];
    const float* Zeta    = (const float*)d_in[5];
    const float* ShfA    = (const float*)d_in[6];
    const float* ShfZ    = (const float*)d_in[7];
    float* out = (float*)d_out;

    int B = in_sizes[0] / AA;   // species is [B, A]
    aev_kernel<<<B * AA, 256>>>(species, coords, EtaR, ShfR, EtaA, Zeta,
                                ShfA, ShfZ, out);
}